// round 9
// baseline (speedup 1.0000x reference)
#include <cuda_runtime.h>
#include <cuda_fp16.h>

#define N_I 500000
#define N_H 200000
#define F_I 32
#define F_H 16
#define EF  8
#define E1  2000000
#define E2  2000000

// ---- pre kernel geometry (depth-3 block pipeline, static smem <= 48KB) ----
#define TILE_I  96                      // indivi nodes per tile
#define TILE_H  160                     // house nodes per tile
#define NTI     5209                    // ceil(N_I/96)
#define NTH     1250                    // N_H/160 exact
#define TPB_I   9                       // tiles per indivi block
#define TPB_H   8                       // tiles per house block
#define PREB_I  579                     // ceil(5209/9)
#define PREB_H  157                     // ceil(1250/8)
#define SI      36                      // staged indivi row stride (16B-mult)
#define SH      20                      // staged house row stride (16B-mult)
#define BUF_FL  3456                    // floats/buffer >= max(96*36, 160*20)

// Packed per-source-node record, 32 B (one L2 sector):
//  [0..3]=y as 8x fp16 pairs, [4]=z fp32, [5..7] pad
__device__ __align__(32) float g_rec_h[(size_t)N_H * 8];
__device__ __align__(32) float g_rec_i[(size_t)N_I * 8];

__device__ __forceinline__ float pack2h(float a, float b) {
    __half2 h = __floats2half2_rn(a, b);
    return __uint_as_float(*reinterpret_cast<unsigned*>(&h));
}
__device__ __forceinline__ unsigned smem_u32(const void* p) {
    return (unsigned)__cvta_generic_to_shared(p);
}
__device__ __forceinline__ void cp16(unsigned dst, const void* src) {
    asm volatile("cp.async.ca.shared.global [%0], [%1], 16;\n" :: "r"(dst), "l"(src));
}
__device__ __forceinline__ void cp_commit() {
    asm volatile("cp.async.commit_group;\n" ::: "memory");
}
__device__ __forceinline__ void cp_wait2() {
    asm volatile("cp.async.wait_group 2;\n" ::: "memory");
}
__device__ __forceinline__ void cp_wait1() {
    asm volatile("cp.async.wait_group 1;\n" ::: "memory");
}
__device__ __forceinline__ void cp_wait0() {
    asm volatile("cp.async.wait_group 0;\n" ::: "memory");
}

// ==========================================================================
// Pre kernel: depth-3 cp.async pipeline per block.
//   blocks [0, PREB_I): indivi — rec_i + out[n] = root
//   blocks [PREB_I, +PREB_H): house — rec_h
// ==========================================================================
__global__ void __launch_bounds__(256)
pre_kernel(const float* __restrict__ x_indivi,
           const float* __restrict__ x_house,
           const float* __restrict__ W_edge_i,  // [F_I, EF]
           const float* __restrict__ b_edge_i,  // [F_I]
           const float* __restrict__ W_edge_h,  // [F_H, EF]
           const float* __restrict__ b_edge_h,  // [F_H]
           const float* __restrict__ W_root_h,  // [1, F_I]
           const float* __restrict__ W_root_i,  // [1, F_I]
           const float* __restrict__ bias_h,    // [1]
           const float* __restrict__ bias_i,    // [1]
           float* __restrict__ out)
{
    __shared__ float sbuf[3][BUF_FL];    // 41.5 KB
    __shared__ float sW[F_I * EF];
    __shared__ float sb[F_I];
    __shared__ float sWr[F_I];
    __shared__ float sbias;

    int t    = threadIdx.x;
    int wid  = t >> 5;
    int lane = t & 31;

    if (blockIdx.x < PREB_I) {
        // ================== indivi region ==================
        sW[t] = W_edge_i[t];
        if (t < F_I) {
            sb[t]  = b_edge_i[t];
            sWr[t] = W_root_h[t] + W_root_i[t];
        }
        if (t == 0) sbias = bias_h[0] + bias_i[0];

        int tile0 = blockIdx.x * TPB_I;
        int ntiles = NTI - tile0;
        if (ntiles > TPB_I) ntiles = TPB_I;
        if (ntiles <= 0) return;

        const float4* x4 = reinterpret_cast<const float4*>(x_indivi);
        const long gmax = (long)N_I * (F_I / 4);

        auto issue = [&](int tile, int buf) {
            long base_f4 = (long)tile * TILE_I * (F_I / 4);
            unsigned s32 = smem_u32(sbuf[buf]);
#pragma unroll
            for (int i = 0; i < 3; i++) {              // 768 float4 / 256 thr
                int  loc  = t + i * 256;
                long gidx = base_f4 + loc;
                if (gidx < gmax) {
                    int row = loc >> 3, col = loc & 7;
                    cp16(s32 + (row * SI + col * 4) * 4, x4 + gidx);
                }
            }
            cp_commit();
        };

        int issued = 0;
        for (; issued < 3 && issued < ntiles; issued++)
            issue(tile0 + issued, issued);

        int idx12 = lane & 15;
        int half  = lane >> 4;
        int f0    = half * 16;
        int nl    = wid * 12 + (idx12 < 12 ? idx12 : 0);  // clamped for smem

        for (int tt = 0; tt < ntiles; tt++) {
            int rem = ntiles - tt;
            if (rem >= 3)      cp_wait2();
            else if (rem == 2) cp_wait1();
            else               cp_wait0();
            __syncthreads();

            const float* xr = sbuf[tt % 3] + nl * SI + f0;
            float y[EF];
#pragma unroll
            for (int k = 0; k < EF; k++) y[k] = 0.f;
            float z = 0.f, root = 0.f;
#pragma unroll
            for (int j = 0; j < 16; j++) {
                float xf = xr[j];
                int f = f0 + j;
#pragma unroll
                for (int k = 0; k < EF; k++) y[k] = fmaf(xf, sW[f*EF + k], y[k]);
                z    = fmaf(xf, sb[f],  z);
                root = fmaf(xf, sWr[f], root);
            }
#pragma unroll
            for (int k = 0; k < EF; k++)
                y[k] += __shfl_down_sync(0xffffffffu, y[k], 16);
            z    += __shfl_down_sync(0xffffffffu, z, 16);
            root += __shfl_down_sync(0xffffffffu, root, 16);

            int n = (tile0 + tt) * TILE_I + wid * 12 + idx12;
            if (half == 0 && idx12 < 12 && n < N_I) {
                float4* ro = reinterpret_cast<float4*>(g_rec_i + (size_t)n * 8);
                ro[0] = make_float4(pack2h(y[0], y[1]), pack2h(y[2], y[3]),
                                    pack2h(y[4], y[5]), pack2h(y[6], y[7]));
                ro[1] = make_float4(z, 0.f, 0.f, 0.f);
                out[n] = root + sbias;
            }
            __syncthreads();                     // buffer free for reuse
            if (issued < ntiles) {
                issue(tile0 + issued, issued % 3);
                issued++;
            }
        }
    } else {
        // ================== house region ==================
        if (t < F_H * EF) sW[t] = W_edge_h[t];
        if (t < F_H)      sb[t] = b_edge_h[t];

        int tile0 = (blockIdx.x - PREB_I) * TPB_H;
        int ntiles = NTH - tile0;
        if (ntiles > TPB_H) ntiles = TPB_H;
        if (ntiles <= 0) return;

        const float4* x4 = reinterpret_cast<const float4*>(x_house);
        const long gmax = (long)N_H * (F_H / 4);

        auto issue = [&](int tile, int buf) {
            long base_f4 = (long)tile * TILE_H * (F_H / 4);
            unsigned s32 = smem_u32(sbuf[buf]);
#pragma unroll
            for (int i = 0; i < 3; i++) {              // 640 float4 / 256 thr
                int loc = t + i * 256;
                if (loc < TILE_H * (F_H / 4)) {
                    long gidx = base_f4 + loc;
                    if (gidx < gmax) {
                        int row = loc >> 2, col = loc & 3;
                        cp16(s32 + (row * SH + col * 4) * 4, x4 + gidx);
                    }
                }
            }
            cp_commit();
        };

        int issued = 0;
        for (; issued < 3 && issued < ntiles; issued++)
            issue(tile0 + issued, issued);

        for (int tt = 0; tt < ntiles; tt++) {
            int rem = ntiles - tt;
            if (rem >= 3)      cp_wait2();
            else if (rem == 2) cp_wait1();
            else               cp_wait0();
            __syncthreads();

            if (t < TILE_H) {
                int n = (tile0 + tt) * TILE_H + t;
                if (n < N_H) {
                    const float* xr = sbuf[tt % 3] + t * SH;
                    float y[EF];
#pragma unroll
                    for (int k = 0; k < EF; k++) y[k] = 0.f;
                    float z = 0.f;
#pragma unroll
                    for (int f = 0; f < F_H; f++) {
                        float xf = xr[f];
#pragma unroll
                        for (int k = 0; k < EF; k++)
                            y[k] = fmaf(xf, sW[f*EF + k], y[k]);
                        z = fmaf(xf, sb[f], z);
                    }
                    float4* ro = reinterpret_cast<float4*>(g_rec_h + (size_t)n * 8);
                    ro[0] = make_float4(pack2h(y[0], y[1]), pack2h(y[2], y[3]),
                                        pack2h(y[4], y[5]), pack2h(y[6], y[7]));
                    ro[1] = make_float4(z, 0.f, 0.f, 0.f);
                }
            }
            __syncthreads();
            if (issued < ntiles) {
                issue(tile0 + issued, issued % 3);
                issued++;
            }
        }
    }
}

// ==========================================================================
// Edge kernel: both relations, 1 edge/thread (R3 exact form, known-fast).
// ==========================================================================
__device__ __forceinline__ void
edge_body(const float* __restrict__ ea, const int* __restrict__ src,
          const int* __restrict__ dst, const float* __restrict__ rec,
          float* __restrict__ out, int e)
{
    int s = __ldg(src + e);
    int d = __ldg(dst + e);

    const float4* ar = reinterpret_cast<const float4*>(ea + (size_t)e * EF);
    float4 a0 = __ldg(ar);
    float4 a1 = __ldg(ar + 1);

    float4 v = __ldg(reinterpret_cast<const float4*>(rec + (size_t)s * 8));
    float  z = __ldg(rec + (size_t)s * 8 + 4);     // same 32B sector

    float2 f01 = __half22float2(*reinterpret_cast<__half2*>(&v.x));
    float2 f23 = __half22float2(*reinterpret_cast<__half2*>(&v.y));
    float2 f45 = __half22float2(*reinterpret_cast<__half2*>(&v.z));
    float2 f67 = __half22float2(*reinterpret_cast<__half2*>(&v.w));

    float m = z;
    m = fmaf(a0.x, f01.x, m);
    m = fmaf(a0.y, f01.y, m);
    m = fmaf(a0.z, f23.x, m);
    m = fmaf(a0.w, f23.y, m);
    m = fmaf(a1.x, f45.x, m);
    m = fmaf(a1.y, f45.y, m);
    m = fmaf(a1.z, f67.x, m);
    m = fmaf(a1.w, f67.y, m);

    atomicAdd(out + d, m);
}

__global__ void __launch_bounds__(256)
edge_fused_kernel(const float* __restrict__ ea1,
                  const int*   __restrict__ src1,
                  const int*   __restrict__ dst1,
                  const float* __restrict__ ea2,
                  const int*   __restrict__ src2,
                  const int*   __restrict__ dst2,
                  float* __restrict__ out)
{
    int e = blockIdx.x * 256 + threadIdx.x;
    if (e < E1) {
        edge_body(ea1, src1, dst1, g_rec_h, out, e);
    } else {
        int e2 = e - E1;
        if (e2 < E2)
            edge_body(ea2, src2, dst2, g_rec_i, out, e2);
    }
}

// ==========================================================================
extern "C" void kernel_launch(void* const* d_in, const int* in_sizes, int n_in,
                              void* d_out, int out_size)
{
    const float* x_indivi      = (const float*)d_in[0];
    const float* x_house       = (const float*)d_in[1];
    const float* edge_attr_h2i = (const float*)d_in[2];
    const float* edge_attr_i2i = (const float*)d_in[3];
    const float* W_edge_h2i    = (const float*)d_in[4];
    const float* b_edge_h2i    = (const float*)d_in[5];
    const float* W_edge_i2i    = (const float*)d_in[6];
    const float* b_edge_i2i    = (const float*)d_in[7];
    const float* W_root_h2i    = (const float*)d_in[8];
    const float* bias_h2i      = (const float*)d_in[9];
    const float* W_root_i2i    = (const float*)d_in[10];
    const float* bias_i2i      = (const float*)d_in[11];
    const int*   src_h2i       = (const int*)d_in[12];
    const int*   dst_h2i       = (const int*)d_in[13];
    const int*   src_i2i       = (const int*)d_in[14];
    const int*   dst_i2i       = (const int*)d_in[15];
    float* out = (float*)d_out;

    pre_kernel<<<PREB_I + PREB_H, 256>>>(
        x_indivi, x_house, W_edge_i2i, b_edge_i2i, W_edge_h2i, b_edge_h2i,
        W_root_h2i, W_root_i2i, bias_h2i, bias_i2i, out);

    int total_edges = E1 + E2;
    edge_fused_kernel<<<(total_edges + 255) / 256, 256>>>(
        edge_attr_h2i, src_h2i, dst_h2i,
        edge_attr_i2i, src_i2i, dst_i2i, out);
}

// round 10
// speedup vs baseline: 1.0499x; 1.0499x over previous
#include <cuda_runtime.h>
#include <cuda_fp16.h>

#define N_I 500000
#define N_H 200000
#define F_I 32
#define F_H 16
#define EF  8
#define E1  2000000
#define E2  2000000

// ---- pre kernel geometry (R7 depth-2 block pipeline — measured best) ----
#define TILE_I   128          // indivi nodes per tile (1024 float4)
#define TILES_PER_BLK_I 8
#define NTILE_I  3907         // ceil(N_I/128)
#define PREB_I   489          // ceil(3907/8)
#define TILE_H   256          // house nodes per tile (1024 float4)
#define TILES_PER_BLK_H 4
#define NTILE_H  782          // ceil(N_H/256)
#define PREB_H   196          // ceil(782/4)
#define STRIDE_I 36
#define STRIDE_H 20
#define SBUF_FLOATS 5248

// Packed per-source-node record, 32 B (one L2 sector):
//  [0..3]=y as 8x fp16 pairs, [4]=z fp32, [5..7] pad
__device__ __align__(32) float g_rec_h[(size_t)N_H * 8];
__device__ __align__(32) float g_rec_i[(size_t)N_I * 8];

__device__ __forceinline__ float pack2h(float a, float b) {
    __half2 h = __floats2half2_rn(a, b);
    return __uint_as_float(*reinterpret_cast<unsigned*>(&h));
}
__device__ __forceinline__ unsigned smem_u32(const void* p) {
    return (unsigned)__cvta_generic_to_shared(p);
}
__device__ __forceinline__ void cp16(unsigned dst, const void* src) {
    asm volatile("cp.async.ca.shared.global [%0], [%1], 16;\n" :: "r"(dst), "l"(src));
}
__device__ __forceinline__ void cp_commit() {
    asm volatile("cp.async.commit_group;\n" ::: "memory");
}
__device__ __forceinline__ void cp_wait1() {
    asm volatile("cp.async.wait_group 1;\n" ::: "memory");
}
__device__ __forceinline__ void cp_wait0() {
    asm volatile("cp.async.wait_group 0;\n" ::: "memory");
}

// ==========================================================================
// Pre kernel (R7 exact): cp.async double-buffered multi-tile pipeline.
//   blocks [0, PREB_I): indivi — rec_i + out[n] = root (direct store)
//   blocks [PREB_I, +PREB_H): house — rec_h
// ==========================================================================
__global__ void __launch_bounds__(256)
pre_kernel(const float* __restrict__ x_indivi,
           const float* __restrict__ x_house,
           const float* __restrict__ W_edge_i,  // [F_I, EF]
           const float* __restrict__ b_edge_i,  // [F_I]
           const float* __restrict__ W_edge_h,  // [F_H, EF]
           const float* __restrict__ b_edge_h,  // [F_H]
           const float* __restrict__ W_root_h,  // [1, F_I]
           const float* __restrict__ W_root_i,  // [1, F_I]
           const float* __restrict__ bias_h,    // [1]
           const float* __restrict__ bias_i,    // [1]
           float* __restrict__ out)
{
    __shared__ float sbuf[2][SBUF_FLOATS];
    __shared__ float sW[F_I * EF];
    __shared__ float sb[F_I];
    __shared__ float sWr[F_I];
    __shared__ float sbias;

    int t = threadIdx.x;

    if (blockIdx.x < PREB_I) {
        // ---------------- indivi region ----------------
        sW[t] = W_edge_i[t];                    // 256 == F_I*EF
        if (t < F_I) {
            sb[t]  = b_edge_i[t];
            sWr[t] = W_root_h[t] + W_root_i[t];
        }
        if (t == 0) sbias = bias_h[0] + bias_i[0];

        int tile0 = blockIdx.x * TILES_PER_BLK_I;
        const long gmax = (long)N_I * (F_I / 4);        // float4 count
        const float4* x4 = reinterpret_cast<const float4*>(x_indivi);

        auto issue_i = [&](int j, int buf) {
            long base_f4 = (long)(tile0 + j) * TILE_I * (F_I / 4);
            unsigned sb32 = smem_u32(sbuf[buf]);
#pragma unroll
            for (int i = 0; i < 4; i++) {
                int  loc  = t + i * 256;
                long gidx = base_f4 + loc;
                if (gidx < gmax) {
                    int row = loc >> 3, col = loc & 7;
                    cp16(sb32 + (row * STRIDE_I + col * 4) * 4, x4 + gidx);
                }
            }
            cp_commit();
        };

        int ntiles = NTILE_I - tile0;
        if (ntiles > TILES_PER_BLK_I) ntiles = TILES_PER_BLK_I;
        if (ntiles <= 0) return;

        issue_i(0, 0);
        __syncthreads();   // sW/sb ready

        int warp = t >> 5, lane = t & 31;
        int node_local = warp * 16 + (lane & 15);
        int half = lane >> 4;
        int f0 = half * 16;

        for (int tt = 0; tt < ntiles; tt++) {
            if (tt + 1 < ntiles) { issue_i(tt + 1, (tt + 1) & 1); cp_wait1(); }
            else                 { cp_wait0(); }
            __syncthreads();

            const float* xr = sbuf[tt & 1] + node_local * STRIDE_I + f0;
            float y[EF];
#pragma unroll
            for (int k = 0; k < EF; k++) y[k] = 0.f;
            float z = 0.f, root = 0.f;
#pragma unroll
            for (int j = 0; j < 16; j++) {
                float xf = xr[j];
                int f = f0 + j;
#pragma unroll
                for (int k = 0; k < EF; k++) y[k] = fmaf(xf, sW[f*EF + k], y[k]);
                z    = fmaf(xf, sb[f],  z);
                root = fmaf(xf, sWr[f], root);
            }
#pragma unroll
            for (int k = 0; k < EF; k++)
                y[k] += __shfl_down_sync(0xffffffffu, y[k], 16);
            z    += __shfl_down_sync(0xffffffffu, z, 16);
            root += __shfl_down_sync(0xffffffffu, root, 16);

            int n = (tile0 + tt) * TILE_I + node_local;
            if (half == 0 && n < N_I) {
                float4* ro = reinterpret_cast<float4*>(g_rec_i + (size_t)n * 8);
                ro[0] = make_float4(pack2h(y[0], y[1]), pack2h(y[2], y[3]),
                                    pack2h(y[4], y[5]), pack2h(y[6], y[7]));
                ro[1] = make_float4(z, 0.f, 0.f, 0.f);
                out[n] = root + sbias;
            }
            __syncthreads();
        }
    } else {
        // ---------------- house region ----------------
        if (t < F_H * EF) sW[t] = W_edge_h[t];
        if (t < F_H)      sb[t] = b_edge_h[t];

        int tile0 = (blockIdx.x - PREB_I) * TILES_PER_BLK_H;
        const long gmax = (long)N_H * (F_H / 4);
        const float4* x4 = reinterpret_cast<const float4*>(x_house);

        auto issue_h = [&](int j, int buf) {
            long base_f4 = (long)(tile0 + j) * TILE_H * (F_H / 4);
            unsigned sb32 = smem_u32(sbuf[buf]);
#pragma unroll
            for (int i = 0; i < 4; i++) {
                int  loc  = t + i * 256;
                long gidx = base_f4 + loc;
                if (gidx < gmax) {
                    int row = loc >> 2, col = loc & 3;
                    cp16(sb32 + (row * STRIDE_H + col * 4) * 4, x4 + gidx);
                }
            }
            cp_commit();
        };

        int ntiles = NTILE_H - tile0;
        if (ntiles > TILES_PER_BLK_H) ntiles = TILES_PER_BLK_H;
        if (ntiles <= 0) return;

        issue_h(0, 0);
        __syncthreads();

        for (int tt = 0; tt < ntiles; tt++) {
            if (tt + 1 < ntiles) { issue_h(tt + 1, (tt + 1) & 1); cp_wait1(); }
            else                 { cp_wait0(); }
            __syncthreads();

            int n = (tile0 + tt) * TILE_H + t;
            if (n < N_H) {
                const float* xr = sbuf[tt & 1] + t * STRIDE_H;
                float y[EF];
#pragma unroll
                for (int k = 0; k < EF; k++) y[k] = 0.f;
                float z = 0.f;
#pragma unroll
                for (int f = 0; f < F_H; f++) {
                    float xf = xr[f];
#pragma unroll
                    for (int k = 0; k < EF; k++) y[k] = fmaf(xf, sW[f*EF + k], y[k]);
                    z = fmaf(xf, sb[f], z);
                }
                float4* ro = reinterpret_cast<float4*>(g_rec_h + (size_t)n * 8);
                ro[0] = make_float4(pack2h(y[0], y[1]), pack2h(y[2], y[3]),
                                    pack2h(y[4], y[5]), pack2h(y[6], y[7]));
                ro[1] = make_float4(z, 0.f, 0.f, 0.f);
            }
            __syncthreads();
        }
    }
}

// ==========================================================================
// Edge kernel (R3 exact): both relations, 1 edge/thread.
// ==========================================================================
__device__ __forceinline__ void
edge_body(const float* __restrict__ ea, const int* __restrict__ src,
          const int* __restrict__ dst, const float* __restrict__ rec,
          float* __restrict__ out, int e)
{
    int s = __ldg(src + e);
    int d = __ldg(dst + e);

    const float4* ar = reinterpret_cast<const float4*>(ea + (size_t)e * EF);
    float4 a0 = __ldg(ar);
    float4 a1 = __ldg(ar + 1);

    float4 v = __ldg(reinterpret_cast<const float4*>(rec + (size_t)s * 8));
    float  z = __ldg(rec + (size_t)s * 8 + 4);     // same 32B sector

    float2 f01 = __half22float2(*reinterpret_cast<__half2*>(&v.x));
    float2 f23 = __half22float2(*reinterpret_cast<__half2*>(&v.y));
    float2 f45 = __half22float2(*reinterpret_cast<__half2*>(&v.z));
    float2 f67 = __half22float2(*reinterpret_cast<__half2*>(&v.w));

    float m = z;
    m = fmaf(a0.x, f01.x, m);
    m = fmaf(a0.y, f01.y, m);
    m = fmaf(a0.z, f23.x, m);
    m = fmaf(a0.w, f23.y, m);
    m = fmaf(a1.x, f45.x, m);
    m = fmaf(a1.y, f45.y, m);
    m = fmaf(a1.z, f67.x, m);
    m = fmaf(a1.w, f67.y, m);

    atomicAdd(out + d, m);
}

__global__ void __launch_bounds__(256)
edge_fused_kernel(const float* __restrict__ ea1,
                  const int*   __restrict__ src1,
                  const int*   __restrict__ dst1,
                  const float* __restrict__ ea2,
                  const int*   __restrict__ src2,
                  const int*   __restrict__ dst2,
                  float* __restrict__ out)
{
    int e = blockIdx.x * 256 + threadIdx.x;
    if (e < E1) {
        edge_body(ea1, src1, dst1, g_rec_h, out, e);
    } else {
        int e2 = e - E1;
        if (e2 < E2)
            edge_body(ea2, src2, dst2, g_rec_i, out, e2);
    }
}

// ==========================================================================
extern "C" void kernel_launch(void* const* d_in, const int* in_sizes, int n_in,
                              void* d_out, int out_size)
{
    const float* x_indivi      = (const float*)d_in[0];
    const float* x_house       = (const float*)d_in[1];
    const float* edge_attr_h2i = (const float*)d_in[2];
    const float* edge_attr_i2i = (const float*)d_in[3];
    const float* W_edge_h2i    = (const float*)d_in[4];
    const float* b_edge_h2i    = (const float*)d_in[5];
    const float* W_edge_i2i    = (const float*)d_in[6];
    const float* b_edge_i2i    = (const float*)d_in[7];
    const float* W_root_h2i    = (const float*)d_in[8];
    const float* bias_h2i      = (const float*)d_in[9];
    const float* W_root_i2i    = (const float*)d_in[10];
    const float* bias_i2i      = (const float*)d_in[11];
    const int*   src_h2i       = (const int*)d_in[12];
    const int*   dst_h2i       = (const int*)d_in[13];
    const int*   src_i2i       = (const int*)d_in[14];
    const int*   dst_i2i       = (const int*)d_in[15];
    float* out = (float*)d_out;

    pre_kernel<<<PREB_I + PREB_H, 256>>>(
        x_indivi, x_house, W_edge_i2i, b_edge_i2i, W_edge_h2i, b_edge_h2i,
        W_root_h2i, W_root_i2i, bias_h2i, bias_i2i, out);

    int total_edges = E1 + E2;
    edge_fused_kernel<<<(total_edges + 255) / 256, 256>>>(
        edge_attr_h2i, src_h2i, dst_h2i,
        edge_attr_i2i, src_i2i, dst_i2i, out);
}

// round 11
// speedup vs baseline: 1.0742x; 1.0231x over previous
#include <cuda_runtime.h>
#include <cuda_fp16.h>

#define N_I 500000
#define N_H 200000
#define F_I 32
#define F_H 16
#define EF  8
#define E1  2000000
#define E2  2000000

// ---- pre kernel geometry (depth-2 block pipeline) ----
#define TILE_I   128
#define TILES_PER_BLK_I 8
#define NTILE_I  3907
#define PREB_I   489
#define TILE_H   256
#define TILES_PER_BLK_H 4
#define NTILE_H  782
#define PREB_H   196
#define STRIDE_I 36
#define STRIDE_H 20
#define SBUF_FLOATS 5248

// Packed per-source-node record, 32 B (one L2 sector):
//  [0..3]=y as 8x fp16 pairs, [4]=z fp32, [5..7] pad
__device__ __align__(32) float g_rec_h[(size_t)N_H * 8];
__device__ __align__(32) float g_rec_i[(size_t)N_I * 8];

__device__ __forceinline__ float pack2h(float a, float b) {
    __half2 h = __floats2half2_rn(a, b);
    return __uint_as_float(*reinterpret_cast<unsigned*>(&h));
}
__device__ __forceinline__ unsigned smem_u32(const void* p) {
    return (unsigned)__cvta_generic_to_shared(p);
}
__device__ __forceinline__ void cp16(unsigned dst, const void* src) {
    asm volatile("cp.async.ca.shared.global [%0], [%1], 16;\n" :: "r"(dst), "l"(src));
}
__device__ __forceinline__ void cp_commit() {
    asm volatile("cp.async.commit_group;\n" ::: "memory");
}
__device__ __forceinline__ void cp_wait1() {
    asm volatile("cp.async.wait_group 1;\n" ::: "memory");
}
__device__ __forceinline__ void cp_wait0() {
    asm volatile("cp.async.wait_group 0;\n" ::: "memory");
}

// ---- packed f32x2 helpers (FFMA2 — PTX-only, ptxas won't auto-fuse) ----
__device__ __forceinline__ unsigned long long pk2(float lo, float hi) {
    unsigned long long r;
    asm("mov.b64 %0, {%1, %2};" : "=l"(r) : "f"(lo), "f"(hi));
    return r;
}
__device__ __forceinline__ void upk2(float& lo, float& hi, unsigned long long v) {
    asm("mov.b64 {%0, %1}, %2;" : "=f"(lo), "=f"(hi) : "l"(v));
}
__device__ __forceinline__ unsigned long long
fma2(unsigned long long a, unsigned long long b, unsigned long long c) {
    unsigned long long d;
    asm("fma.rn.f32x2 %0, %1, %2, %3;" : "=l"(d) : "l"(a), "l"(b), "l"(c));
    return d;
}

// ==========================================================================
// Pre kernel: depth-2 cp.async pipeline + packed f32x2 accumulation.
//   blocks [0, PREB_I): indivi — rec_i + out[n] = root
//   blocks [PREB_I, +PREB_H): house — rec_h
// ==========================================================================
__global__ void __launch_bounds__(256)
pre_kernel(const float* __restrict__ x_indivi,
           const float* __restrict__ x_house,
           const float* __restrict__ W_edge_i,  // [F_I, EF]
           const float* __restrict__ b_edge_i,  // [F_I]
           const float* __restrict__ W_edge_h,  // [F_H, EF]
           const float* __restrict__ b_edge_h,  // [F_H]
           const float* __restrict__ W_root_h,  // [1, F_I]
           const float* __restrict__ W_root_i,  // [1, F_I]
           const float* __restrict__ bias_h,    // [1]
           const float* __restrict__ bias_i,    // [1]
           float* __restrict__ out)
{
    __shared__ float sbuf[2][SBUF_FLOATS];
    __shared__ float sW[F_I * EF];       // row-major [f][k] — pairs contiguous
    __shared__ float sbr[F_I * 2];       // [2f]=b_edge, [2f+1]=Wroot sum
    __shared__ float sbias;

    int t = threadIdx.x;

    if (blockIdx.x < PREB_I) {
        // ---------------- indivi region ----------------
        sW[t] = W_edge_i[t];
        if (t < F_I) {
            sbr[2*t]   = b_edge_i[t];
            sbr[2*t+1] = W_root_h[t] + W_root_i[t];
        }
        if (t == 0) sbias = bias_h[0] + bias_i[0];

        int tile0 = blockIdx.x * TILES_PER_BLK_I;
        const long gmax = (long)N_I * (F_I / 4);
        const float4* x4 = reinterpret_cast<const float4*>(x_indivi);

        auto issue_i = [&](int j, int buf) {
            long base_f4 = (long)(tile0 + j) * TILE_I * (F_I / 4);
            unsigned sb32 = smem_u32(sbuf[buf]);
#pragma unroll
            for (int i = 0; i < 4; i++) {
                int  loc  = t + i * 256;
                long gidx = base_f4 + loc;
                if (gidx < gmax) {
                    int row = loc >> 3, col = loc & 7;
                    cp16(sb32 + (row * STRIDE_I + col * 4) * 4, x4 + gidx);
                }
            }
            cp_commit();
        };

        int ntiles = NTILE_I - tile0;
        if (ntiles > TILES_PER_BLK_I) ntiles = TILES_PER_BLK_I;
        if (ntiles <= 0) return;

        issue_i(0, 0);
        __syncthreads();

        int warp = t >> 5, lane = t & 31;
        int node_local = warp * 16 + (lane & 15);
        int half = lane >> 4;
        int f0 = half * 16;

        const unsigned long long* w2 =
            reinterpret_cast<const unsigned long long*>(sW);
        const unsigned long long* br2 =
            reinterpret_cast<const unsigned long long*>(sbr);

        for (int tt = 0; tt < ntiles; tt++) {
            if (tt + 1 < ntiles) { issue_i(tt + 1, (tt + 1) & 1); cp_wait1(); }
            else                 { cp_wait0(); }
            __syncthreads();

            // load 16 features via 4x LDS.128
            const float4* xr4 = reinterpret_cast<const float4*>(
                sbuf[tt & 1] + node_local * STRIDE_I + f0);
            float x[16];
#pragma unroll
            for (int i = 0; i < 4; i++) {
                float4 v = xr4[i];
                x[4*i+0] = v.x; x[4*i+1] = v.y; x[4*i+2] = v.z; x[4*i+3] = v.w;
            }

            unsigned long long y2[4];
#pragma unroll
            for (int k = 0; k < 4; k++) y2[k] = 0ull;
            unsigned long long zr = 0ull;       // (z, root)
#pragma unroll
            for (int j = 0; j < 16; j++) {
                int f = f0 + j;
                unsigned long long xf2 = pk2(x[j], x[j]);
                const unsigned long long* wr = w2 + f * (EF / 2);
#pragma unroll
                for (int k = 0; k < 4; k++) y2[k] = fma2(xf2, wr[k], y2[k]);
                zr = fma2(xf2, br2[f], zr);
            }

            float y[EF];
#pragma unroll
            for (int k = 0; k < 4; k++) upk2(y[2*k], y[2*k+1], y2[k]);
            float z, root;
            upk2(z, root, zr);

#pragma unroll
            for (int k = 0; k < EF; k++)
                y[k] += __shfl_down_sync(0xffffffffu, y[k], 16);
            z    += __shfl_down_sync(0xffffffffu, z, 16);
            root += __shfl_down_sync(0xffffffffu, root, 16);

            int n = (tile0 + tt) * TILE_I + node_local;
            if (half == 0 && n < N_I) {
                float4* ro = reinterpret_cast<float4*>(g_rec_i + (size_t)n * 8);
                ro[0] = make_float4(pack2h(y[0], y[1]), pack2h(y[2], y[3]),
                                    pack2h(y[4], y[5]), pack2h(y[6], y[7]));
                ro[1] = make_float4(z, 0.f, 0.f, 0.f);
                out[n] = root + sbias;
            }
            __syncthreads();
        }
    } else {
        // ---------------- house region ----------------
        if (t < F_H * EF) sW[t] = W_edge_h[t];
        if (t < F_H) {
            sbr[2*t]   = b_edge_h[t];
            sbr[2*t+1] = 0.f;
        }

        int tile0 = (blockIdx.x - PREB_I) * TILES_PER_BLK_H;
        const long gmax = (long)N_H * (F_H / 4);
        const float4* x4 = reinterpret_cast<const float4*>(x_house);

        auto issue_h = [&](int j, int buf) {
            long base_f4 = (long)(tile0 + j) * TILE_H * (F_H / 4);
            unsigned sb32 = smem_u32(sbuf[buf]);
#pragma unroll
            for (int i = 0; i < 4; i++) {
                int  loc  = t + i * 256;
                long gidx = base_f4 + loc;
                if (gidx < gmax) {
                    int row = loc >> 2, col = loc & 3;
                    cp16(sb32 + (row * STRIDE_H + col * 4) * 4, x4 + gidx);
                }
            }
            cp_commit();
        };

        int ntiles = NTILE_H - tile0;
        if (ntiles > TILES_PER_BLK_H) ntiles = TILES_PER_BLK_H;
        if (ntiles <= 0) return;

        issue_h(0, 0);
        __syncthreads();

        const unsigned long long* w2 =
            reinterpret_cast<const unsigned long long*>(sW);
        const unsigned long long* br2 =
            reinterpret_cast<const unsigned long long*>(sbr);

        for (int tt = 0; tt < ntiles; tt++) {
            if (tt + 1 < ntiles) { issue_h(tt + 1, (tt + 1) & 1); cp_wait1(); }
            else                 { cp_wait0(); }
            __syncthreads();

            int n = (tile0 + tt) * TILE_H + t;
            if (n < N_H) {
                const float4* xr4 = reinterpret_cast<const float4*>(
                    sbuf[tt & 1] + t * STRIDE_H);
                float x[16];
#pragma unroll
                for (int i = 0; i < 4; i++) {
                    float4 v = xr4[i];
                    x[4*i+0] = v.x; x[4*i+1] = v.y;
                    x[4*i+2] = v.z; x[4*i+3] = v.w;
                }

                unsigned long long y2[4];
#pragma unroll
                for (int k = 0; k < 4; k++) y2[k] = 0ull;
                unsigned long long zr = 0ull;
#pragma unroll
                for (int f = 0; f < F_H; f++) {
                    unsigned long long xf2 = pk2(x[f], x[f]);
                    const unsigned long long* wr = w2 + f * (EF / 2);
#pragma unroll
                    for (int k = 0; k < 4; k++) y2[k] = fma2(xf2, wr[k], y2[k]);
                    zr = fma2(xf2, br2[f], zr);
                }
                float y[EF];
#pragma unroll
                for (int k = 0; k < 4; k++) upk2(y[2*k], y[2*k+1], y2[k]);
                float z, dummy;
                upk2(z, dummy, zr);

                float4* ro = reinterpret_cast<float4*>(g_rec_h + (size_t)n * 8);
                ro[0] = make_float4(pack2h(y[0], y[1]), pack2h(y[2], y[3]),
                                    pack2h(y[4], y[5]), pack2h(y[6], y[7]));
                ro[1] = make_float4(z, 0.f, 0.f, 0.f);
            }
            __syncthreads();
        }
    }
}

// ==========================================================================
// Edge kernel: 1 edge/thread; __ldcs (evict-first) on streaming operands
// so the rec tables stay L2-resident for the random gathers.
// ==========================================================================
__device__ __forceinline__ void
edge_body(const float* __restrict__ ea, const int* __restrict__ src,
          const int* __restrict__ dst, const float* __restrict__ rec,
          float* __restrict__ out, int e)
{
    int s = __ldcs(src + e);
    int d = __ldcs(dst + e);

    const float4* ar = reinterpret_cast<const float4*>(ea + (size_t)e * EF);
    float4 a0 = __ldcs(ar);
    float4 a1 = __ldcs(ar + 1);

    float4 v = __ldg(reinterpret_cast<const float4*>(rec + (size_t)s * 8));
    float  z = __ldg(rec + (size_t)s * 8 + 4);     // same 32B sector

    float2 f01 = __half22float2(*reinterpret_cast<__half2*>(&v.x));
    float2 f23 = __half22float2(*reinterpret_cast<__half2*>(&v.y));
    float2 f45 = __half22float2(*reinterpret_cast<__half2*>(&v.z));
    float2 f67 = __half22float2(*reinterpret_cast<__half2*>(&v.w));

    float m = z;
    m = fmaf(a0.x, f01.x, m);
    m = fmaf(a0.y, f01.y, m);
    m = fmaf(a0.z, f23.x, m);
    m = fmaf(a0.w, f23.y, m);
    m = fmaf(a1.x, f45.x, m);
    m = fmaf(a1.y, f45.y, m);
    m = fmaf(a1.z, f67.x, m);
    m = fmaf(a1.w, f67.y, m);

    atomicAdd(out + d, m);
}

__global__ void __launch_bounds__(256)
edge_fused_kernel(const float* __restrict__ ea1,
                  const int*   __restrict__ src1,
                  const int*   __restrict__ dst1,
                  const float* __restrict__ ea2,
                  const int*   __restrict__ src2,
                  const int*   __restrict__ dst2,
                  float* __restrict__ out)
{
    int e = blockIdx.x * 256 + threadIdx.x;
    if (e < E1) {
        edge_body(ea1, src1, dst1, g_rec_h, out, e);
    } else {
        int e2 = e - E1;
        if (e2 < E2)
            edge_body(ea2, src2, dst2, g_rec_i, out, e2);
    }
}

// ==========================================================================
extern "C" void kernel_launch(void* const* d_in, const int* in_sizes, int n_in,
                              void* d_out, int out_size)
{
    const float* x_indivi      = (const float*)d_in[0];
    const float* x_house       = (const float*)d_in[1];
    const float* edge_attr_h2i = (const float*)d_in[2];
    const float* edge_attr_i2i = (const float*)d_in[3];
    const float* W_edge_h2i    = (const float*)d_in[4];
    const float* b_edge_h2i    = (const float*)d_in[5];
    const float* W_edge_i2i    = (const float*)d_in[6];
    const float* b_edge_i2i    = (const float*)d_in[7];
    const float* W_root_h2i    = (const float*)d_in[8];
    const float* bias_h2i      = (const float*)d_in[9];
    const float* W_root_i2i    = (const float*)d_in[10];
    const float* bias_i2i      = (const float*)d_in[11];
    const int*   src_h2i       = (const int*)d_in[12];
    const int*   dst_h2i       = (const int*)d_in[13];
    const int*   src_i2i       = (const int*)d_in[14];
    const int*   dst_i2i       = (const int*)d_in[15];
    float* out = (float*)d_out;

    pre_kernel<<<PREB_I + PREB_H, 256>>>(
        x_indivi, x_house, W_edge_i2i, b_edge_i2i, W_edge_h2i, b_edge_h2i,
        W_root_h2i, W_root_i2i, bias_h2i, bias_i2i, out);

    int total_edges = E1 + E2;
    edge_fused_kernel<<<(total_edges + 255) / 256, 256>>>(
        edge_attr_h2i, src_h2i, dst_h2i,
        edge_attr_i2i, src_i2i, dst_i2i, out);
}

// round 13
// speedup vs baseline: 1.1362x; 1.0578x over previous
#include <cuda_runtime.h>
#include <cuda_fp16.h>

#define N_I 500000
#define N_H 200000
#define F_I 32
#define F_H 16
#define EF  8
#define E1  2000000
#define E2  2000000

// ---- pre kernel geometry: 256-node tiles, 1 node/thread, single buffer ----
#define TI     256
#define NT_I   1954          // ceil(N_I/256)
#define NT_H   782           // ceil(N_H/256)
#define TPBK   4             // tiles per block
#define PB_I   489           // ceil(1954/4)
#define PB_H   196           // ceil(782/4)
#define SI     36            // staged indivi row stride (floats, 16B-mult)
#define SH     20            // staged house row stride

// Packed per-source-node record, 32 B (one L2 sector):
//  [0..3]=y as 8x fp16 pairs, [4]=z fp32, [5..7] pad
__device__ __align__(32) float g_rec_h[(size_t)N_H * 8];
__device__ __align__(32) float g_rec_i[(size_t)N_I * 8];

__device__ __forceinline__ float pack2h(float a, float b) {
    __half2 h = __floats2half2_rn(a, b);
    return __uint_as_float(*reinterpret_cast<unsigned*>(&h));
}
__device__ __forceinline__ unsigned smem_u32(const void* p) {
    return (unsigned)__cvta_generic_to_shared(p);
}
__device__ __forceinline__ void cp16(unsigned dst, const void* src) {
    asm volatile("cp.async.cg.shared.global [%0], [%1], 16;\n" :: "r"(dst), "l"(src));
}
__device__ __forceinline__ void cp_commit() {
    asm volatile("cp.async.commit_group;\n" ::: "memory");
}
__device__ __forceinline__ void cp_wait0() {
    asm volatile("cp.async.wait_group 0;\n" ::: "memory");
}

// ---- packed f32x2 helpers (FFMA2 — PTX-only) ----
__device__ __forceinline__ unsigned long long pk2(float lo, float hi) {
    unsigned long long r;
    asm("mov.b64 %0, {%1, %2};" : "=l"(r) : "f"(lo), "f"(hi));
    return r;
}
__device__ __forceinline__ void upk2(float& lo, float& hi, unsigned long long v) {
    asm("mov.b64 {%0, %1}, %2;" : "=f"(lo), "=f"(hi) : "l"(v));
}
__device__ __forceinline__ unsigned long long
fma2(unsigned long long a, unsigned long long b, unsigned long long c) {
    unsigned long long d;
    asm("fma.rn.f32x2 %0, %1, %2, %3;" : "=l"(d) : "l"(a), "l"(b), "l"(c));
    return d;
}

// ==========================================================================
// Pre kernel: 1 node/thread, 256-node tiles, single buffer, cross-block
// overlap. blocks [0, PB_I): indivi (rec_i + out root); [PB_I,+PB_H): house.
// Weight pairs: sW row-major [f][k] so 64-bit pair k of row f is
// (W[f*EF+2k], W[f*EF+2k+1]) — multiplied by (x,x) gives y[2k], y[2k+1].
// ==========================================================================
__global__ void __launch_bounds__(256)
pre_kernel(const float* __restrict__ x_indivi,
           const float* __restrict__ x_house,
           const float* __restrict__ W_edge_i,  // [F_I, EF]
           const float* __restrict__ b_edge_i,  // [F_I]
           const float* __restrict__ W_edge_h,  // [F_H, EF]
           const float* __restrict__ b_edge_h,  // [F_H]
           const float* __restrict__ W_root_h,  // [1, F_I]
           const float* __restrict__ W_root_i,  // [1, F_I]
           const float* __restrict__ bias_h,    // [1]
           const float* __restrict__ bias_i,    // [1]
           float* __restrict__ out)
{
    __shared__ float sbuf[TI * SI];          // 36.9 KB (house uses prefix)
    __shared__ float sW[F_I * EF];           // row-major, pairs contiguous
    __shared__ float sbr[F_I * 2];           // (b_edge, Wroot-sum) pairs
    __shared__ float sbias;

    int t = threadIdx.x;

    if (blockIdx.x < PB_I) {
        // ================= indivi region =================
        sW[t] = W_edge_i[t];                 // 256 == F_I*EF
        if (t < F_I) {
            sbr[2*t]   = b_edge_i[t];
            sbr[2*t+1] = W_root_h[t] + W_root_i[t];
        }
        if (t == 0) sbias = bias_h[0] + bias_i[0];

        int tile0 = blockIdx.x * TPBK;
        int ntiles = NT_I - tile0;
        if (ntiles > TPBK) ntiles = TPBK;
        if (ntiles <= 0) return;

        const float4* x4 = reinterpret_cast<const float4*>(x_indivi);
        const long gmax = (long)N_I * (F_I / 4);
        const unsigned long long* w2 =
            reinterpret_cast<const unsigned long long*>(sW);
        const unsigned long long* br2 =
            reinterpret_cast<const unsigned long long*>(sbr);

        for (int tt = 0; tt < ntiles; tt++) {
            // stage tile: 2048 float4, 8 per thread
            {
                long base_f4 = (long)(tile0 + tt) * TI * (F_I / 4);
                unsigned s32 = smem_u32(sbuf);
#pragma unroll
                for (int i = 0; i < 8; i++) {
                    int  loc  = t + i * 256;
                    long gidx = base_f4 + loc;
                    if (gidx < gmax) {
                        int row = loc >> 3, col = loc & 7;
                        cp16(s32 + (row * SI + col * 4) * 4, x4 + gidx);
                    }
                }
                cp_commit();
            }
            cp_wait0();
            __syncthreads();                 // data (+weights on first iter)

            int n = (tile0 + tt) * TI + t;
            if (n < N_I) {
                const float4* xr4 = reinterpret_cast<const float4*>(sbuf + t * SI);
                unsigned long long y2[4] = {0ull, 0ull, 0ull, 0ull};
                unsigned long long zr = 0ull;    // (z, root)
#pragma unroll
                for (int g = 0; g < 8; g++) {
                    float4 v = xr4[g];
                    float xs[4] = {v.x, v.y, v.z, v.w};
#pragma unroll
                    for (int j = 0; j < 4; j++) {
                        int f = 4*g + j;
                        unsigned long long xf2 = pk2(xs[j], xs[j]);
                        const unsigned long long* wr = w2 + f * (EF / 2);
#pragma unroll
                        for (int k = 0; k < 4; k++)
                            y2[k] = fma2(xf2, wr[k], y2[k]);
                        zr = fma2(xf2, br2[f], zr);
                    }
                }
                float y[EF];
#pragma unroll
                for (int k = 0; k < 4; k++) upk2(y[2*k], y[2*k+1], y2[k]);
                float z, root;
                upk2(z, root, zr);

                float4* ro = reinterpret_cast<float4*>(g_rec_i + (size_t)n * 8);
                ro[0] = make_float4(pack2h(y[0], y[1]), pack2h(y[2], y[3]),
                                    pack2h(y[4], y[5]), pack2h(y[6], y[7]));
                ro[1] = make_float4(z, 0.f, 0.f, 0.f);
                out[n] = root + sbias;
            }
            __syncthreads();                 // sbuf free before next stage
        }
    } else {
        // ================= house region =================
        if (t < F_H * EF) sW[t] = W_edge_h[t];
        if (t < F_H) {
            sbr[2*t]   = b_edge_h[t];
            sbr[2*t+1] = 0.f;
        }

        int tile0 = (blockIdx.x - PB_I) * TPBK;
        int ntiles = NT_H - tile0;
        if (ntiles > TPBK) ntiles = TPBK;
        if (ntiles <= 0) return;

        const float4* x4 = reinterpret_cast<const float4*>(x_house);
        const long gmax = (long)N_H * (F_H / 4);
        const unsigned long long* w2 =
            reinterpret_cast<const unsigned long long*>(sW);
        const unsigned long long* br2 =
            reinterpret_cast<const unsigned long long*>(sbr);

        for (int tt = 0; tt < ntiles; tt++) {
            {
                long base_f4 = (long)(tile0 + tt) * TI * (F_H / 4);
                unsigned s32 = smem_u32(sbuf);
#pragma unroll
                for (int i = 0; i < 4; i++) {     // 1024 float4, 4 per thread
                    int  loc  = t + i * 256;
                    long gidx = base_f4 + loc;
                    if (gidx < gmax) {
                        int row = loc >> 2, col = loc & 3;
                        cp16(s32 + (row * SH + col * 4) * 4, x4 + gidx);
                    }
                }
                cp_commit();
            }
            cp_wait0();
            __syncthreads();

            int n = (tile0 + tt) * TI + t;
            if (n < N_H) {
                const float4* xr4 = reinterpret_cast<const float4*>(sbuf + t * SH);
                unsigned long long y2[4] = {0ull, 0ull, 0ull, 0ull};
                unsigned long long zr = 0ull;
#pragma unroll
                for (int g = 0; g < 4; g++) {
                    float4 v = xr4[g];
                    float xs[4] = {v.x, v.y, v.z, v.w};
#pragma unroll
                    for (int j = 0; j < 4; j++) {
                        int f = 4*g + j;
                        unsigned long long xf2 = pk2(xs[j], xs[j]);
                        const unsigned long long* wr = w2 + f * (EF / 2);
#pragma unroll
                        for (int k = 0; k < 4; k++)
                            y2[k] = fma2(xf2, wr[k], y2[k]);
                        zr = fma2(xf2, br2[f], zr);
                    }
                }
                float y[EF];
#pragma unroll
                for (int k = 0; k < 4; k++) upk2(y[2*k], y[2*k+1], y2[k]);
                float z, dummy;
                upk2(z, dummy, zr);

                float4* ro = reinterpret_cast<float4*>(g_rec_h + (size_t)n * 8);
                ro[0] = make_float4(pack2h(y[0], y[1]), pack2h(y[2], y[3]),
                                    pack2h(y[4], y[5]), pack2h(y[6], y[7]));
                ro[1] = make_float4(z, 0.f, 0.f, 0.f);
            }
            __syncthreads();
        }
    }
}

// ==========================================================================
// Edge kernel (R11 exact): 1 edge/thread, __ldcs streams, single-sector
// record gather, atomic scatter.
// ==========================================================================
__device__ __forceinline__ void
edge_body(const float* __restrict__ ea, const int* __restrict__ src,
          const int* __restrict__ dst, const float* __restrict__ rec,
          float* __restrict__ out, int e)
{
    int s = __ldcs(src + e);
    int d = __ldcs(dst + e);

    const float4* ar = reinterpret_cast<const float4*>(ea + (size_t)e * EF);
    float4 a0 = __ldcs(ar);
    float4 a1 = __ldcs(ar + 1);

    float4 v = __ldg(reinterpret_cast<const float4*>(rec + (size_t)s * 8));
    float  z = __ldg(rec + (size_t)s * 8 + 4);     // same 32B sector

    float2 f01 = __half22float2(*reinterpret_cast<__half2*>(&v.x));
    float2 f23 = __half22float2(*reinterpret_cast<__half2*>(&v.y));
    float2 f45 = __half22float2(*reinterpret_cast<__half2*>(&v.z));
    float2 f67 = __half22float2(*reinterpret_cast<__half2*>(&v.w));

    float m = z;
    m = fmaf(a0.x, f01.x, m);
    m = fmaf(a0.y, f01.y, m);
    m = fmaf(a0.z, f23.x, m);
    m = fmaf(a0.w, f23.y, m);
    m = fmaf(a1.x, f45.x, m);
    m = fmaf(a1.y, f45.y, m);
    m = fmaf(a1.z, f67.x, m);
    m = fmaf(a1.w, f67.y, m);

    atomicAdd(out + d, m);
}

__global__ void __launch_bounds__(256)
edge_fused_kernel(const float* __restrict__ ea1,
                  const int*   __restrict__ src1,
                  const int*   __restrict__ dst1,
                  const float* __restrict__ ea2,
                  const int*   __restrict__ src2,
                  const int*   __restrict__ dst2,
                  float* __restrict__ out)
{
    int e = blockIdx.x * 256 + threadIdx.x;
    if (e < E1) {
        edge_body(ea1, src1, dst1, g_rec_h, out, e);
    } else {
        int e2 = e - E1;
        if (e2 < E2)
            edge_body(ea2, src2, dst2, g_rec_i, out, e2);
    }
}

// ==========================================================================
extern "C" void kernel_launch(void* const* d_in, const int* in_sizes, int n_in,
                              void* d_out, int out_size)
{
    const float* x_indivi      = (const float*)d_in[0];
    const float* x_house       = (const float*)d_in[1];
    const float* edge_attr_h2i = (const float*)d_in[2];
    const float* edge_attr_i2i = (const float*)d_in[3];
    const float* W_edge_h2i    = (const float*)d_in[4];
    const float* b_edge_h2i    = (const float*)d_in[5];
    const float* W_edge_i2i    = (const float*)d_in[6];
    const float* b_edge_i2i    = (const float*)d_in[7];
    const float* W_root_h2i    = (const float*)d_in[8];
    const float* bias_h2i      = (const float*)d_in[9];
    const float* W_root_i2i    = (const float*)d_in[10];
    const float* bias_i2i      = (const float*)d_in[11];
    const int*   src_h2i       = (const int*)d_in[12];
    const int*   dst_h2i       = (const int*)d_in[13];
    const int*   src_i2i       = (const int*)d_in[14];
    const int*   dst_i2i       = (const int*)d_in[15];
    float* out = (float*)d_out;

    pre_kernel<<<PB_I + PB_H, 256>>>(
        x_indivi, x_house, W_edge_i2i, b_edge_i2i, W_edge_h2i, b_edge_h2i,
        W_root_h2i, W_root_i2i, bias_h2i, bias_i2i, out);

    int total_edges = E1 + E2;
    edge_fused_kernel<<<(total_edges + 255) / 256, 256>>>(
        edge_attr_h2i, src_h2i, dst_h2i,
        edge_attr_i2i, src_i2i, dst_i2i, out);
}

// round 14
// speedup vs baseline: 1.1514x; 1.0133x over previous
#include <cuda_runtime.h>
#include <cuda_fp16.h>

#define N_I 500000
#define N_H 200000
#define F_I 32
#define F_H 16
#define EF  8
#define E1  2000000
#define E2  2000000

// ---- pre kernel geometry: 256-node tiles, 1 node/thread, single buffer ----
#define TI     256
#define NT_I   1954          // ceil(N_I/256)
#define NT_H   782           // ceil(N_H/256)
#define TPBK   4             // tiles per block
#define PB_I   489           // ceil(1954/4)
#define PB_H   196           // ceil(782/4)
#define SI     36            // staged indivi row stride (floats, 16B-mult)
#define SH     20            // staged house row stride

// Packed per-source-node record, 32 B (one L2 sector):
//  [0..3]=y as 8x fp16 pairs, [4]=z fp32, [5..7] pad
__device__ __align__(32) float g_rec_h[(size_t)N_H * 8];
__device__ __align__(32) float g_rec_i[(size_t)N_I * 8];

__device__ __forceinline__ float pack2h(float a, float b) {
    __half2 h = __floats2half2_rn(a, b);
    return __uint_as_float(*reinterpret_cast<unsigned*>(&h));
}
__device__ __forceinline__ unsigned smem_u32(const void* p) {
    return (unsigned)__cvta_generic_to_shared(p);
}
__device__ __forceinline__ void cp16(unsigned dst, const void* src) {
    asm volatile("cp.async.cg.shared.global [%0], [%1], 16;\n" :: "r"(dst), "l"(src));
}
__device__ __forceinline__ void cp_commit() {
    asm volatile("cp.async.commit_group;\n" ::: "memory");
}
__device__ __forceinline__ void cp_wait0() {
    asm volatile("cp.async.wait_group 0;\n" ::: "memory");
}

// ---- packed f32x2 helpers (FFMA2 — PTX-only) ----
__device__ __forceinline__ unsigned long long pk2(float lo, float hi) {
    unsigned long long r;
    asm("mov.b64 %0, {%1, %2};" : "=l"(r) : "f"(lo), "f"(hi));
    return r;
}
__device__ __forceinline__ void upk2(float& lo, float& hi, unsigned long long v) {
    asm("mov.b64 {%0, %1}, %2;" : "=f"(lo), "=f"(hi) : "l"(v));
}
__device__ __forceinline__ unsigned long long
fma2(unsigned long long a, unsigned long long b, unsigned long long c) {
    unsigned long long d;
    asm("fma.rn.f32x2 %0, %1, %2, %3;" : "=l"(d) : "l"(a), "l"(b), "l"(c));
    return d;
}

// ==========================================================================
// Pre kernel: 1 node/thread, 256-node tiles, single buffer, intra-tile
// software pipeline: drain tile into registers -> sync -> issue next tile's
// cp.async -> compute. Next DRAM fetch overlaps current FMA+stores.
// blocks [0, PB_I): indivi (rec_i + out root); [PB_I, +PB_H): house.
// ==========================================================================
__global__ void __launch_bounds__(256)
pre_kernel(const float* __restrict__ x_indivi,
           const float* __restrict__ x_house,
           const float* __restrict__ W_edge_i,  // [F_I, EF]
           const float* __restrict__ b_edge_i,  // [F_I]
           const float* __restrict__ W_edge_h,  // [F_H, EF]
           const float* __restrict__ b_edge_h,  // [F_H]
           const float* __restrict__ W_root_h,  // [1, F_I]
           const float* __restrict__ W_root_i,  // [1, F_I]
           const float* __restrict__ bias_h,    // [1]
           const float* __restrict__ bias_i,    // [1]
           float* __restrict__ out)
{
    __shared__ float sbuf[TI * SI];          // 36.9 KB (house uses prefix)
    __shared__ float sW[F_I * EF];           // row-major, pairs contiguous
    __shared__ float sbr[F_I * 2];           // (b_edge, Wroot-sum) pairs
    __shared__ float sbias;

    int t = threadIdx.x;

    if (blockIdx.x < PB_I) {
        // ================= indivi region =================
        sW[t] = W_edge_i[t];                 // 256 == F_I*EF
        if (t < F_I) {
            sbr[2*t]   = b_edge_i[t];
            sbr[2*t+1] = W_root_h[t] + W_root_i[t];
        }
        if (t == 0) sbias = bias_h[0] + bias_i[0];

        int tile0 = blockIdx.x * TPBK;
        int ntiles = NT_I - tile0;
        if (ntiles > TPBK) ntiles = TPBK;
        if (ntiles <= 0) return;

        const float4* x4 = reinterpret_cast<const float4*>(x_indivi);
        const long gmax = (long)N_I * (F_I / 4);
        const unsigned long long* w2 =
            reinterpret_cast<const unsigned long long*>(sW);
        const unsigned long long* br2 =
            reinterpret_cast<const unsigned long long*>(sbr);

        auto issue_i = [&](int tt) {
            long base_f4 = (long)(tile0 + tt) * TI * (F_I / 4);
            unsigned s32 = smem_u32(sbuf);
#pragma unroll
            for (int i = 0; i < 8; i++) {
                int  loc  = t + i * 256;
                long gidx = base_f4 + loc;
                if (gidx < gmax) {
                    int row = loc >> 3, col = loc & 7;
                    cp16(s32 + (row * SI + col * 4) * 4, x4 + gidx);
                }
            }
            cp_commit();
        };

        issue_i(0);

        for (int tt = 0; tt < ntiles; tt++) {
            cp_wait0();
            __syncthreads();                 // tile staged (+weights on 1st)

            int n = (tile0 + tt) * TI + t;
            bool act = n < N_I;

            // drain entire row into registers
            float4 xv[8];
            if (act) {
                const float4* xr4 =
                    reinterpret_cast<const float4*>(sbuf + t * SI);
#pragma unroll
                for (int g = 0; g < 8; g++) xv[g] = xr4[g];
            }
            __syncthreads();                 // all smem reads complete

            if (tt + 1 < ntiles) issue_i(tt + 1);   // overlaps compute below

            if (act) {
                unsigned long long y2[4] = {0ull, 0ull, 0ull, 0ull};
                unsigned long long zr = 0ull;    // (z, root)
#pragma unroll
                for (int g = 0; g < 8; g++) {
                    float xs[4] = {xv[g].x, xv[g].y, xv[g].z, xv[g].w};
#pragma unroll
                    for (int j = 0; j < 4; j++) {
                        int f = 4*g + j;
                        unsigned long long xf2 = pk2(xs[j], xs[j]);
                        const unsigned long long* wr = w2 + f * (EF / 2);
#pragma unroll
                        for (int k = 0; k < 4; k++)
                            y2[k] = fma2(xf2, wr[k], y2[k]);
                        zr = fma2(xf2, br2[f], zr);
                    }
                }
                float y[EF];
#pragma unroll
                for (int k = 0; k < 4; k++) upk2(y[2*k], y[2*k+1], y2[k]);
                float z, root;
                upk2(z, root, zr);

                float4* ro = reinterpret_cast<float4*>(g_rec_i + (size_t)n * 8);
                ro[0] = make_float4(pack2h(y[0], y[1]), pack2h(y[2], y[3]),
                                    pack2h(y[4], y[5]), pack2h(y[6], y[7]));
                ro[1] = make_float4(z, 0.f, 0.f, 0.f);
                out[n] = root + sbias;
            }
        }
    } else {
        // ================= house region =================
        if (t < F_H * EF) sW[t] = W_edge_h[t];
        if (t < F_H) {
            sbr[2*t]   = b_edge_h[t];
            sbr[2*t+1] = 0.f;
        }

        int tile0 = (blockIdx.x - PB_I) * TPBK;
        int ntiles = NT_H - tile0;
        if (ntiles > TPBK) ntiles = TPBK;
        if (ntiles <= 0) return;

        const float4* x4 = reinterpret_cast<const float4*>(x_house);
        const long gmax = (long)N_H * (F_H / 4);
        const unsigned long long* w2 =
            reinterpret_cast<const unsigned long long*>(sW);
        const unsigned long long* br2 =
            reinterpret_cast<const unsigned long long*>(sbr);

        auto issue_h = [&](int tt) {
            long base_f4 = (long)(tile0 + tt) * TI * (F_H / 4);
            unsigned s32 = smem_u32(sbuf);
#pragma unroll
            for (int i = 0; i < 4; i++) {     // 1024 float4, 4 per thread
                int  loc  = t + i * 256;
                long gidx = base_f4 + loc;
                if (gidx < gmax) {
                    int row = loc >> 2, col = loc & 3;
                    cp16(s32 + (row * SH + col * 4) * 4, x4 + gidx);
                }
            }
            cp_commit();
        };

        issue_h(0);

        for (int tt = 0; tt < ntiles; tt++) {
            cp_wait0();
            __syncthreads();

            int n = (tile0 + tt) * TI + t;
            bool act = n < N_H;

            float4 xv[4];
            if (act) {
                const float4* xr4 =
                    reinterpret_cast<const float4*>(sbuf + t * SH);
#pragma unroll
                for (int g = 0; g < 4; g++) xv[g] = xr4[g];
            }
            __syncthreads();

            if (tt + 1 < ntiles) issue_h(tt + 1);

            if (act) {
                unsigned long long y2[4] = {0ull, 0ull, 0ull, 0ull};
                unsigned long long zr = 0ull;
#pragma unroll
                for (int g = 0; g < 4; g++) {
                    float xs[4] = {xv[g].x, xv[g].y, xv[g].z, xv[g].w};
#pragma unroll
                    for (int j = 0; j < 4; j++) {
                        int f = 4*g + j;
                        unsigned long long xf2 = pk2(xs[j], xs[j]);
                        const unsigned long long* wr = w2 + f * (EF / 2);
#pragma unroll
                        for (int k = 0; k < 4; k++)
                            y2[k] = fma2(xf2, wr[k], y2[k]);
                        zr = fma2(xf2, br2[f], zr);
                    }
                }
                float y[EF];
#pragma unroll
                for (int k = 0; k < 4; k++) upk2(y[2*k], y[2*k+1], y2[k]);
                float z, dummy;
                upk2(z, dummy, zr);

                float4* ro = reinterpret_cast<float4*>(g_rec_h + (size_t)n * 8);
                ro[0] = make_float4(pack2h(y[0], y[1]), pack2h(y[2], y[3]),
                                    pack2h(y[4], y[5]), pack2h(y[6], y[7]));
                ro[1] = make_float4(z, 0.f, 0.f, 0.f);
            }
        }
    }
}

// ==========================================================================
// Edge kernel (R13 exact): 1 edge/thread, __ldcs streams, single-sector
// record gather, atomic scatter. At its LTS floor — do not touch.
// ==========================================================================
__device__ __forceinline__ void
edge_body(const float* __restrict__ ea, const int* __restrict__ src,
          const int* __restrict__ dst, const float* __restrict__ rec,
          float* __restrict__ out, int e)
{
    int s = __ldcs(src + e);
    int d = __ldcs(dst + e);

    const float4* ar = reinterpret_cast<const float4*>(ea + (size_t)e * EF);
    float4 a0 = __ldcs(ar);
    float4 a1 = __ldcs(ar + 1);

    float4 v = __ldg(reinterpret_cast<const float4*>(rec + (size_t)s * 8));
    float  z = __ldg(rec + (size_t)s * 8 + 4);     // same 32B sector

    float2 f01 = __half22float2(*reinterpret_cast<__half2*>(&v.x));
    float2 f23 = __half22float2(*reinterpret_cast<__half2*>(&v.y));
    float2 f45 = __half22float2(*reinterpret_cast<__half2*>(&v.z));
    float2 f67 = __half22float2(*reinterpret_cast<__half2*>(&v.w));

    float m = z;
    m = fmaf(a0.x, f01.x, m);
    m = fmaf(a0.y, f01.y, m);
    m = fmaf(a0.z, f23.x, m);
    m = fmaf(a0.w, f23.y, m);
    m = fmaf(a1.x, f45.x, m);
    m = fmaf(a1.y, f45.y, m);
    m = fmaf(a1.z, f67.x, m);
    m = fmaf(a1.w, f67.y, m);

    atomicAdd(out + d, m);
}

__global__ void __launch_bounds__(256)
edge_fused_kernel(const float* __restrict__ ea1,
                  const int*   __restrict__ src1,
                  const int*   __restrict__ dst1,
                  const float* __restrict__ ea2,
                  const int*   __restrict__ src2,
                  const int*   __restrict__ dst2,
                  float* __restrict__ out)
{
    int e = blockIdx.x * 256 + threadIdx.x;
    if (e < E1) {
        edge_body(ea1, src1, dst1, g_rec_h, out, e);
    } else {
        int e2 = e - E1;
        if (e2 < E2)
            edge_body(ea2, src2, dst2, g_rec_i, out, e2);
    }
}

// ==========================================================================
extern "C" void kernel_launch(void* const* d_in, const int* in_sizes, int n_in,
                              void* d_out, int out_size)
{
    const float* x_indivi      = (const float*)d_in[0];
    const float* x_house       = (const float*)d_in[1];
    const float* edge_attr_h2i = (const float*)d_in[2];
    const float* edge_attr_i2i = (const float*)d_in[3];
    const float* W_edge_h2i    = (const float*)d_in[4];
    const float* b_edge_h2i    = (const float*)d_in[5];
    const float* W_edge_i2i    = (const float*)d_in[6];
    const float* b_edge_i2i    = (const float*)d_in[7];
    const float* W_root_h2i    = (const float*)d_in[8];
    const float* bias_h2i      = (const float*)d_in[9];
    const float* W_root_i2i    = (const float*)d_in[10];
    const float* bias_i2i      = (const float*)d_in[11];
    const int*   src_h2i       = (const int*)d_in[12];
    const int*   dst_h2i       = (const int*)d_in[13];
    const int*   src_i2i       = (const int*)d_in[14];
    const int*   dst_i2i       = (const int*)d_in[15];
    float* out = (float*)d_out;

    pre_kernel<<<PB_I + PB_H, 256>>>(
        x_indivi, x_house, W_edge_i2i, b_edge_i2i, W_edge_h2i, b_edge_h2i,
        W_root_h2i, W_root_i2i, bias_h2i, bias_i2i, out);

    int total_edges = E1 + E2;
    edge_fused_kernel<<<(total_edges + 255) / 256, 256>>>(
        edge_attr_h2i, src_h2i, dst_h2i,
        edge_attr_i2i, src_i2i, dst_i2i, out);
}